// round 1
// baseline (speedup 1.0000x reference)
#include <cuda_runtime.h>
#include <cstdint>

#define NB_B 4096
#define ND 16
#define NM 4
#define NR 2048
#define NC 10
#define NDP1 17

// Scratch (device globals are the allowed scratch mechanism)
__device__ float    g_cons_sum[NR * NC];
__device__ unsigned g_rpack[NR];
__device__ float    g_sx[NB_B];
__device__ float    g_norm_scratch[(size_t)NB_B * NR]; // used only if harness wants just `out`

// ---------------------------------------------------------------------------
// K0: pack rules (2 bits per dim -> one uint32 per rule) and reduce
//     consequents over j: cons_sum[r,c] = sum_j consequents[r,j,c]
// ---------------------------------------------------------------------------
__global__ void prep_kernel(const float* __restrict__ cons,
                            const int* __restrict__ rules) {
    int r = blockIdx.x * blockDim.x + threadIdx.x;
    if (r >= NR) return;
    unsigned p = 0;
#pragma unroll
    for (int d = 0; d < ND; ++d)
        p |= ((unsigned)rules[r * ND + d] & 3u) << (2 * d);
    g_rpack[r] = p;
    const float* base = cons + (size_t)r * NDP1 * NC;
#pragma unroll
    for (int c = 0; c < NC; ++c) {
        float s = 0.f;
#pragma unroll
        for (int j = 0; j < NDP1; ++j) s += base[j * NC + c];
        g_cons_sum[r * NC + c] = s;
    }
}

// ---------------------------------------------------------------------------
// K0b: x_ext (optional write) and sx[b] = sum_i x_ext[b,i]
// ---------------------------------------------------------------------------
__global__ void xext_kernel(const float* __restrict__ x,
                            float* __restrict__ xext, int write_xext) {
    int b = blockIdx.x * blockDim.x + threadIdx.x;
    if (b >= NB_B) return;
    float s = 1.f;
#pragma unroll
    for (int j = 0; j < ND; ++j) {
        float v = x[b * ND + j];
        s += v;
        if (write_xext) xext[b * NDP1 + j] = v;
    }
    if (write_xext) xext[b * NDP1 + ND] = 1.f;
    g_sx[b] = s;
}

// ---------------------------------------------------------------------------
// K1: firing strengths + normalization.
// One warp per batch row. Per (b,r): 8 conflict-free smem table lookups
// (pair-packed log-membership tables) + 8 adds + one __expf. fs chunk kept
// in 64 registers so normalization is a free second register pass.
// ---------------------------------------------------------------------------
__global__ __launch_bounds__(128) void fs_kernel(
    const float* __restrict__ x,
    const float* __restrict__ centers,
    const float* __restrict__ widths,
    float* __restrict__ norm_out) {
    __shared__ unsigned s_rp[NR];          // 8 KB, shared by all 4 warps
    __shared__ float    s_e[4][64];        // per-warp raw exponents e[d][m]
    __shared__ float    s_e2[4][8][16];    // per-warp pair tables

    const int tid  = threadIdx.x;
    const int w    = tid >> 5;
    const int lane = tid & 31;
    const int b    = blockIdx.x * 4 + w;

    for (int i = tid; i < NR; i += 128) s_rp[i] = g_rpack[i];

    // e[d][m] = -(x-c)^2 / (2 w^2), 64 entries per warp (2 per lane)
#pragma unroll
    for (int k = lane; k < 64; k += 32) {
        int d = k >> 2, m = k & 3;
        float c  = centers[d * NM + m];
        float wd = widths[d * NM + m];
        float dx = x[b * ND + d] - c;
        s_e[w][k] = -(dx * dx) / (2.f * wd * wd);
    }
    __syncwarp();
    // pair tables: e2[t][i] = e[2t][i&3] + e[2t+1][i>>2]
#pragma unroll
    for (int k = lane; k < 128; k += 32) {
        int t = k >> 4, i = k & 15;
        s_e2[w][t][i] = s_e[w][(2 * t) * 4 + (i & 3)] +
                        s_e[w][(2 * t + 1) * 4 + (i >> 2)];
    }
    __syncthreads(); // orders s_rp load and s_e2 build for everyone

    float fs[64];
    float sum = 0.f;
#pragma unroll
    for (int i = 0; i < 64; ++i) {
        unsigned p = s_rp[i * 32 + lane];
        float s = s_e2[w][0][p & 15];
#pragma unroll
        for (int t = 1; t < 8; ++t)
            s += s_e2[w][t][(p >> (4 * t)) & 15];
        float f = __expf(s);
        fs[i] = f;
        sum += f;
    }
#pragma unroll
    for (int off = 16; off > 0; off >>= 1)
        sum += __shfl_xor_sync(0xffffffffu, sum, off);
    const float inv = 1.f / (sum + 1e-9f);

    float* op = norm_out + (size_t)b * NR + lane;
#pragma unroll
    for (int i = 0; i < 64; ++i)
        op[i * 32] = fs[i] * inv;
}

// ---------------------------------------------------------------------------
// K2: out[b,c] = sx[b] * sum_r norm_fs[b,r] * cons_sum[r,c]
// Block = 256 thr (8 warps) x 4 batches per warp = 32 batches/block.
// cons_sum staged in smem with stride-11 padding (11 coprime 32 ->
// conflict-free row reads). norm_fs reads are fully coalesced.
// ---------------------------------------------------------------------------
__global__ __launch_bounds__(256) void out_kernel(
    const float* __restrict__ norm, float* __restrict__ out) {
    extern __shared__ float s_cons[]; // NR * 11 floats = 90112 B

    const int tid  = threadIdx.x;
    const int w    = tid >> 5;
    const int lane = tid & 31;

    for (int r = tid; r < NR; r += 256) {
#pragma unroll
        for (int c = 0; c < NC; ++c)
            s_cons[r * 11 + c] = g_cons_sum[r * NC + c];
    }
    __syncthreads();

    const int b0 = blockIdx.x * 32 + w * 4;
    float acc[4][NC];
#pragma unroll
    for (int nb = 0; nb < 4; ++nb)
#pragma unroll
        for (int c = 0; c < NC; ++c) acc[nb][c] = 0.f;

    const float* n0 = norm + (size_t)b0 * NR + lane;
#pragma unroll 4
    for (int i = 0; i < 64; ++i) {
        const int r = i * 32 + lane;
        float f0 = n0[i * 32];
        float f1 = n0[(size_t)NR + i * 32];
        float f2 = n0[(size_t)2 * NR + i * 32];
        float f3 = n0[(size_t)3 * NR + i * 32];
        const float* cr = &s_cons[r * 11];
#pragma unroll
        for (int c = 0; c < NC; ++c) {
            float cv = cr[c];
            acc[0][c] += f0 * cv;
            acc[1][c] += f1 * cv;
            acc[2][c] += f2 * cv;
            acc[3][c] += f3 * cv;
        }
    }
#pragma unroll
    for (int off = 16; off > 0; off >>= 1) {
#pragma unroll
        for (int nb = 0; nb < 4; ++nb)
#pragma unroll
            for (int c = 0; c < NC; ++c)
                acc[nb][c] += __shfl_xor_sync(0xffffffffu, acc[nb][c], off);
    }
    if (lane == 0) {
#pragma unroll
        for (int nb = 0; nb < 4; ++nb) {
            float sx = g_sx[b0 + nb];
#pragma unroll
            for (int c = 0; c < NC; ++c)
                out[(size_t)(b0 + nb) * NC + c] = acc[nb][c] * sx;
        }
    }
}

// ---------------------------------------------------------------------------
extern "C" void kernel_launch(void* const* d_in, const int* in_sizes, int n_in,
                              void* d_out, int out_size) {
    const float* x       = (const float*)d_in[0];
    const float* centers = (const float*)d_in[1];
    const float* widths  = (const float*)d_in[2];
    const float* cons    = (const float*)d_in[3];
    const int*   rules   = (const int*)d_in[4];
    float* out = (float*)d_out;

    const long long TOTAL = (long long)NB_B * NC + (long long)NB_B * NR +
                            (long long)NB_B * NDP1;

    float* out_p;
    float* norm_p;
    float* xext_p = nullptr;
    int write_xext = 0;

    if ((long long)out_size == TOTAL) {
        out_p  = out;
        norm_p = out + (size_t)NB_B * NC;
        xext_p = out + (size_t)NB_B * NC + (size_t)NB_B * NR;
        write_xext = 1;
    } else {
        // Harness wants only `out` -> keep norm_fs in scratch.
        out_p = out;
        void* sp = nullptr;
        cudaGetSymbolAddress(&sp, g_norm_scratch);
        norm_p = (float*)sp;
    }

    prep_kernel<<<(NR + 127) / 128, 128>>>(cons, rules);
    xext_kernel<<<(NB_B + 127) / 128, 128>>>(x, xext_p ? xext_p : out_p,
                                             write_xext);
    fs_kernel<<<NB_B / 4, 128>>>(x, centers, widths, norm_p);

    const int smem_bytes = NR * 11 * sizeof(float); // 90112
    cudaFuncSetAttribute(out_kernel, cudaFuncAttributeMaxDynamicSharedMemorySize,
                         smem_bytes);
    out_kernel<<<NB_B / 32, 256, smem_bytes>>>(norm_p, out_p);
}

// round 2
// speedup vs baseline: 1.5887x; 1.5887x over previous
#include <cuda_runtime.h>
#include <cstdint>

#define NB_B 4096
#define ND 16
#define NM 4
#define NR 2048
#define NC 10
#define NDP1 17

// Scratch (device globals are the allowed scratch mechanism)
__device__ float    g_cons_sumT[NC * NR];     // transposed: [c][r]
__device__ unsigned g_rpack[NR];
__device__ float    g_norm_scratch[(size_t)NB_B * NR]; // fallback only

// ---------------------------------------------------------------------------
// K0: pack rules (2 bits/dim -> uint32/rule) and reduce consequents over j,
//     storing TRANSPOSED: cons_sumT[c*NR + r] = sum_j cons[r,j,c]
// ---------------------------------------------------------------------------
__global__ void prep_kernel(const float* __restrict__ cons,
                            const int* __restrict__ rules) {
    int r = blockIdx.x * blockDim.x + threadIdx.x;
    if (r >= NR) return;
    unsigned p = 0;
#pragma unroll
    for (int d = 0; d < ND; ++d)
        p |= ((unsigned)rules[r * ND + d] & 3u) << (2 * d);
    g_rpack[r] = p;
    const float* base = cons + (size_t)r * NDP1 * NC;
#pragma unroll
    for (int c = 0; c < NC; ++c) {
        float s = 0.f;
#pragma unroll
        for (int j = 0; j < NDP1; ++j) s += base[j * NC + c];
        g_cons_sumT[c * NR + r] = s;
    }
}

// ---------------------------------------------------------------------------
// K1 (fused): per warp = one batch row.
//  - build pair-packed log-membership tables (8 tables x 16 entries)
//  - fs[64] in registers: 8 LDS lookups + 8 adds + 1 exp per rule
//  - warp-reduce sum -> inv
//  - second register pass: write norm_fs AND accumulate out[c] from the
//    transposed cons table (lane-consecutive r -> conflict-free LDS)
//  - also emits x_ext and out = sx * acc
// ---------------------------------------------------------------------------
__global__ __launch_bounds__(256, 2) void fused_kernel(
    const float* __restrict__ x,
    const float* __restrict__ centers,
    const float* __restrict__ widths,
    float* __restrict__ norm_out,
    float* __restrict__ xext_out,
    float* __restrict__ out,
    int write_xext) {
    extern __shared__ float s_consT[];        // NC*NR floats = 80 KB
    __shared__ unsigned s_rp[NR];             // 8 KB
    __shared__ float    s_e[8][64];           // 2 KB
    __shared__ float    s_e2[8][8][16];       // 4 KB

    const int tid  = threadIdx.x;
    const int w    = tid >> 5;
    const int lane = tid & 31;
    const int b    = blockIdx.x * 8 + w;

    // cooperative smem fills (vectorized)
    {
        const float4* src = (const float4*)g_cons_sumT;
        float4* dst = (float4*)s_consT;
#pragma unroll
        for (int i = tid; i < (NC * NR) / 4; i += 256) dst[i] = src[i];
        const uint4* rsrc = (const uint4*)g_rpack;
        uint4* rdst = (uint4*)s_rp;
#pragma unroll
        for (int i = tid; i < NR / 4; i += 256) rdst[i] = rsrc[i];
    }

    // x for this batch, one element per lane (lanes 0..15), broadcast later
    float xv = (lane < ND) ? x[b * ND + lane] : 0.f;

    // sx = 1 + sum_d x[b,d]
    float sx = xv;
#pragma unroll
    for (int off = 16; off > 0; off >>= 1)
        sx += __shfl_xor_sync(0xffffffffu, sx, off);
    sx += 1.f;

    if (write_xext) {
        if (lane < ND) xext_out[b * NDP1 + lane] = xv;
        if (lane == ND) xext_out[b * NDP1 + ND] = 1.f;
    }

    // e[d][m] = -(x-c)^2 / (2 w^2), 64 entries per warp (2 per lane)
#pragma unroll
    for (int k = lane; k < 64; k += 32) {
        int d = k >> 2, m = k & 3;
        float c  = centers[d * NM + m];
        float wd = widths[d * NM + m];
        float xd = __shfl_sync(0xffffffffu, xv, d);
        float dx = xd - c;
        s_e[w][k] = -(dx * dx) / (2.f * wd * wd);
    }
    __syncwarp();
    // pair tables: e2[t][i] = e[2t][i&3] + e[2t+1][i>>2]
#pragma unroll
    for (int k = lane; k < 128; k += 32) {
        int t = k >> 4, i = k & 15;
        s_e2[w][t][i] = s_e[w][(2 * t) * 4 + (i & 3)] +
                        s_e[w][(2 * t + 1) * 4 + (i >> 2)];
    }
    __syncthreads(); // cons / rpack / tables all visible

    // pass 1: fs + sum
    float fs[64];
    float sum = 0.f;
#pragma unroll
    for (int i = 0; i < 64; ++i) {
        unsigned p = s_rp[i * 32 + lane];
        float s = s_e2[w][0][p & 15];
#pragma unroll
        for (int t = 1; t < 8; ++t)
            s += s_e2[w][t][(p >> (4 * t)) & 15];
        float f = __expf(s);
        fs[i] = f;
        sum += f;
    }
#pragma unroll
    for (int off = 16; off > 0; off >>= 1)
        sum += __shfl_xor_sync(0xffffffffu, sum, off);
    const float inv = 1.f / (sum + 1e-9f);

    // pass 2: write norm_fs + accumulate output
    float acc[NC];
#pragma unroll
    for (int c = 0; c < NC; ++c) acc[c] = 0.f;

    float* op = norm_out + (size_t)b * NR + lane;
#pragma unroll
    for (int i = 0; i < 64; ++i) {
        float f = fs[i] * inv;
        op[i * 32] = f;
        const int r = i * 32 + lane;
#pragma unroll
        for (int c = 0; c < NC; ++c)
            acc[c] += f * s_consT[c * NR + r];
    }
#pragma unroll
    for (int off = 16; off > 0; off >>= 1)
#pragma unroll
        for (int c = 0; c < NC; ++c)
            acc[c] += __shfl_xor_sync(0xffffffffu, acc[c], off);

    if (lane == 0) {
#pragma unroll
        for (int c = 0; c < NC; ++c)
            out[(size_t)b * NC + c] = acc[c] * sx;
    }
}

// ---------------------------------------------------------------------------
extern "C" void kernel_launch(void* const* d_in, const int* in_sizes, int n_in,
                              void* d_out, int out_size) {
    const float* x       = (const float*)d_in[0];
    const float* centers = (const float*)d_in[1];
    const float* widths  = (const float*)d_in[2];
    const float* cons    = (const float*)d_in[3];
    const int*   rules   = (const int*)d_in[4];
    float* out = (float*)d_out;

    const long long TOTAL = (long long)NB_B * NC + (long long)NB_B * NR +
                            (long long)NB_B * NDP1;

    float* out_p = out;
    float* norm_p;
    float* xext_p = out;
    int write_xext = 0;

    if ((long long)out_size == TOTAL) {
        norm_p = out + (size_t)NB_B * NC;
        xext_p = out + (size_t)NB_B * NC + (size_t)NB_B * NR;
        write_xext = 1;
    } else {
        void* sp = nullptr;
        cudaGetSymbolAddress(&sp, g_norm_scratch);
        norm_p = (float*)sp;
    }

    prep_kernel<<<(NR + 127) / 128, 128>>>(cons, rules);

    const int smem_bytes = NC * NR * sizeof(float); // 81920
    cudaFuncSetAttribute(fused_kernel,
                         cudaFuncAttributeMaxDynamicSharedMemorySize,
                         smem_bytes);
    fused_kernel<<<NB_B / 8, 256, smem_bytes>>>(x, centers, widths, norm_p,
                                                xext_p, out_p, write_xext);
}

// round 3
// speedup vs baseline: 1.6302x; 1.0261x over previous
#include <cuda_runtime.h>
#include <cuda_bf16.h>
#include <cstdint>

#define NB_B 4096
#define ND 16
#define NM 4
#define NR 2048
#define NC 10
#define NDP1 17
#define MU 8.5f

// Scratch (device globals are the allowed scratch mechanism)
__device__ unsigned g_consP[5 * NR];   // plane p: bf16x2 of (cons_sum[r,2p]-MU, cons_sum[r,2p+1]-MU)
__device__ unsigned g_rpack[NR];
__device__ float    g_inv[NB_B];
__device__ float    g_norm_scratch[(size_t)NB_B * NR]; // fallback only

// ---------------------------------------------------------------------------
// K0: rule packing + consequent j-reduction into mean-centered bf16x2 planes.
// threads [0, 5*NR): plane sums; threads [5*NR, 5*NR+NR): rpack.
// ---------------------------------------------------------------------------
__global__ void prep_kernel(const float* __restrict__ cons,
                            const int* __restrict__ rules) {
    int t = blockIdx.x * blockDim.x + threadIdx.x;
    if (t < 5 * NR) {
        int r = t % NR;
        int p = t / NR;
        const float* base = cons + (size_t)r * NDP1 * NC + 2 * p;
        float s0 = 0.f, s1 = 0.f;
#pragma unroll
        for (int j = 0; j < NDP1; ++j) {
            s0 += base[j * NC];
            s1 += base[j * NC + 1];
        }
        __nv_bfloat162 h = __floats2bfloat162_rn(s0 - MU, s1 - MU);
        g_consP[p * NR + r] = *(unsigned*)&h;
    } else if (t < 6 * NR) {
        int r = t - 5 * NR;
        unsigned pk = 0;
#pragma unroll
        for (int d = 0; d < ND; ++d)
            pk |= ((unsigned)rules[r * ND + d] & 3u) << (2 * d);
        g_rpack[r] = pk;
    }
}

// ---------------------------------------------------------------------------
// K1 (fused): warp = one batch row.
//  - pair-packed log-membership tables (8 x 16, conflict-free broadcasts)
//  - per rule-pair: 2x(8 LDS lookups + adds + exp), write UNNORMALIZED f
//    as float2, accumulate out from bf16x2 cons planes (LDS.64)
//  - epilogue: warp-reduce -> inv (stored for scale kernel), out, x_ext
//  smem ~54KB, <=64 regs -> 4 blocks/SM, grid 512 = single wave.
// ---------------------------------------------------------------------------
__global__ __launch_bounds__(256, 4) void fused_kernel(
    const float* __restrict__ x,
    const float* __restrict__ centers,
    const float* __restrict__ widths,
    float* __restrict__ norm_out,
    float* __restrict__ xext_out,
    float* __restrict__ out,
    int write_xext) {
    extern __shared__ unsigned s_cons[];      // 5*NR words = 40 KB
    __shared__ unsigned s_rp[NR];             // 8 KB
    __shared__ float    s_e[8][64];           // 2 KB
    __shared__ float    s_e2[8][8][16];       // 4 KB

    const int tid  = threadIdx.x;
    const int w    = tid >> 5;
    const int lane = tid & 31;
    const int b    = blockIdx.x * 8 + w;

    // cooperative smem fills (vectorized)
    {
        const uint4* src = (const uint4*)g_consP;
        uint4* dst = (uint4*)s_cons;
#pragma unroll
        for (int i = tid; i < (5 * NR) / 4; i += 256) dst[i] = src[i];
        const uint4* rsrc = (const uint4*)g_rpack;
        uint4* rdst = (uint4*)s_rp;
#pragma unroll
        for (int i = tid; i < NR / 4; i += 256) rdst[i] = rsrc[i];
    }

    float xv = (lane < ND) ? x[b * ND + lane] : 0.f;

    float sx = xv;
#pragma unroll
    for (int off = 16; off > 0; off >>= 1)
        sx += __shfl_xor_sync(0xffffffffu, sx, off);
    sx += 1.f;

    if (write_xext) {
        if (lane < ND) xext_out[b * NDP1 + lane] = xv;
        if (lane == ND) xext_out[b * NDP1 + ND] = 1.f;
    }

    // e[d][m] = -(x-c)^2/(2 w^2)
#pragma unroll
    for (int k = lane; k < 64; k += 32) {
        int d = k >> 2, m = k & 3;
        float c  = centers[d * NM + m];
        float wd = widths[d * NM + m];
        float xd = __shfl_sync(0xffffffffu, xv, d);
        float dx = xd - c;
        s_e[w][k] = -(dx * dx) / (2.f * wd * wd);
    }
    __syncwarp();
#pragma unroll
    for (int k = lane; k < 128; k += 32) {
        int t = k >> 4, i = k & 15;
        s_e2[w][t][i] = s_e[w][(2 * t) * 4 + (i & 3)] +
                        s_e[w][(2 * t + 1) * 4 + (i >> 2)];
    }
    __syncthreads();

    float acc[NC];
#pragma unroll
    for (int c = 0; c < NC; ++c) acc[c] = 0.f;
    float sum = 0.f;

    float2* np = (float2*)(norm_out + (size_t)b * NR) + lane;
    const float (*e2)[16] = s_e2[w];

#pragma unroll 4
    for (int i = 0; i < 32; ++i) {
        const int q = i * 32 + lane;              // rule pair index
        uint2 pp = ((const uint2*)s_rp)[q];       // rules 2q, 2q+1
        float s0 = e2[0][pp.x & 15];
        float s1 = e2[0][pp.y & 15];
#pragma unroll
        for (int t = 1; t < 8; ++t) {
            s0 += e2[t][(pp.x >> (4 * t)) & 15];
            s1 += e2[t][(pp.y >> (4 * t)) & 15];
        }
        float f0 = __expf(s0);
        float f1 = __expf(s1);
        sum += f0 + f1;
        np[i * 32] = make_float2(f0, f1);         // unnormalized
#pragma unroll
        for (int p = 0; p < 5; ++p) {
            uint2 cw = ((const uint2*)(s_cons + p * NR))[q];
            float lo0 = __uint_as_float(cw.x << 16);
            float hi0 = __uint_as_float(cw.x & 0xffff0000u);
            float lo1 = __uint_as_float(cw.y << 16);
            float hi1 = __uint_as_float(cw.y & 0xffff0000u);
            acc[2 * p]     = fmaf(f0, lo0, acc[2 * p]);
            acc[2 * p]     = fmaf(f1, lo1, acc[2 * p]);
            acc[2 * p + 1] = fmaf(f0, hi0, acc[2 * p + 1]);
            acc[2 * p + 1] = fmaf(f1, hi1, acc[2 * p + 1]);
        }
    }

#pragma unroll
    for (int off = 16; off > 0; off >>= 1) {
        sum += __shfl_xor_sync(0xffffffffu, sum, off);
#pragma unroll
        for (int c = 0; c < NC; ++c)
            acc[c] += __shfl_xor_sync(0xffffffffu, acc[c], off);
    }
    const float inv = 1.f / (sum + 1e-9f);

    if (lane == 0) {
        g_inv[b] = inv;
        const float k = inv * sx;
#pragma unroll
        for (int c = 0; c < NC; ++c)
            out[(size_t)b * NC + c] = (acc[c] + MU * sum) * k;
    }
}

// ---------------------------------------------------------------------------
// K2: normalize the fs buffer in place: norm[b][r] *= inv[b].
// One block per batch row; data is L2-resident (33.5MB < 126MB L2).
// ---------------------------------------------------------------------------
__global__ __launch_bounds__(128) void scale_kernel(float* __restrict__ norm) {
    const int b = blockIdx.x;
    const float inv = g_inv[b];
    float4* p = (float4*)(norm + (size_t)b * NR);
#pragma unroll
    for (int i = threadIdx.x; i < NR / 4; i += 128) {
        float4 v = p[i];
        v.x *= inv; v.y *= inv; v.z *= inv; v.w *= inv;
        p[i] = v;
    }
}

// ---------------------------------------------------------------------------
extern "C" void kernel_launch(void* const* d_in, const int* in_sizes, int n_in,
                              void* d_out, int out_size) {
    const float* x       = (const float*)d_in[0];
    const float* centers = (const float*)d_in[1];
    const float* widths  = (const float*)d_in[2];
    const float* cons    = (const float*)d_in[3];
    const int*   rules   = (const int*)d_in[4];
    float* out = (float*)d_out;

    const long long TOTAL = (long long)NB_B * NC + (long long)NB_B * NR +
                            (long long)NB_B * NDP1;

    float* out_p = out;
    float* norm_p;
    float* xext_p = out;
    int write_xext = 0;

    if ((long long)out_size == TOTAL) {
        norm_p = out + (size_t)NB_B * NC;
        xext_p = out + (size_t)NB_B * NC + (size_t)NB_B * NR;
        write_xext = 1;
    } else {
        void* sp = nullptr;
        cudaGetSymbolAddress(&sp, g_norm_scratch);
        norm_p = (float*)sp;
    }

    prep_kernel<<<(6 * NR + 255) / 256, 256>>>(cons, rules);

    const int smem_bytes = 5 * NR * sizeof(unsigned); // 40960
    cudaFuncSetAttribute(fused_kernel,
                         cudaFuncAttributeMaxDynamicSharedMemorySize,
                         smem_bytes);
    fused_kernel<<<NB_B / 8, 256, smem_bytes>>>(x, centers, widths, norm_p,
                                                xext_p, out_p, write_xext);
    scale_kernel<<<NB_B, 128>>>(norm_p);
}

// round 4
// speedup vs baseline: 1.7644x; 1.0823x over previous
#include <cuda_runtime.h>
#include <cuda_bf16.h>
#include <cstdint>

#define NB_B 4096
#define ND 16
#define NM 4
#define NR 2048
#define NC 10
#define NDP1 17
#define MU 8.5f

// Scratch (device globals are the allowed scratch mechanism)
__device__ unsigned g_consP[5 * NR];   // plane p: bf16x2 of (cons_sum[r,2p]-MU, cons_sum[r,2p+1]-MU)
__device__ unsigned g_rpack[NR];
__device__ float    g_inv[NB_B];
__device__ float    g_norm_scratch[(size_t)NB_B * NR]; // fallback only

// ---------------------------------------------------------------------------
// K0: coalesced prep. 256 blocks x 256 thr; each block owns 8 rules.
// Stage 8x170 floats + 8x16 ints coalesced into smem, then 40 threads build
// the mean-centered bf16x2 plane sums and 8 threads pack the rule indices.
// ---------------------------------------------------------------------------
__global__ __launch_bounds__(256) void prep_kernel(
    const float* __restrict__ cons, const int* __restrict__ rules) {
    __shared__ float sc[8 * NDP1 * NC];   // 5440 B
    __shared__ int   sr[8 * ND];

    const int tid = threadIdx.x;
    const int r0  = blockIdx.x * 8;

    const float* cbase = cons + (size_t)r0 * NDP1 * NC;
#pragma unroll
    for (int i = tid; i < 8 * NDP1 * NC; i += 256) sc[i] = cbase[i];
    const int* rbase = rules + r0 * ND;
    if (tid < 8 * ND) sr[tid] = rbase[tid];
    __syncthreads();

    if (tid < 40) {
        const int rl = tid / 5, p = tid % 5;
        const float* row = sc + rl * NDP1 * NC + 2 * p;
        float s0 = 0.f, s1 = 0.f;
#pragma unroll
        for (int j = 0; j < NDP1; ++j) {
            s0 += row[j * NC];
            s1 += row[j * NC + 1];
        }
        __nv_bfloat162 h = __floats2bfloat162_rn(s0 - MU, s1 - MU);
        g_consP[p * NR + r0 + rl] = *(unsigned*)&h;
    } else if (tid < 48) {
        const int rl = tid - 40;
        unsigned pk = 0;
#pragma unroll
        for (int d = 0; d < ND; ++d)
            pk |= ((unsigned)sr[rl * ND + d] & 3u) << (2 * d);
        g_rpack[r0 + rl] = pk;
    }
}

// ---------------------------------------------------------------------------
// K1 (fused): warp = one batch row.
//  - pair-packed log-membership tables (8 x 16, conflict-free: each table
//    spans 16 banks exactly once -> same-bank == broadcast)
//  - per rule-pair: 16 lookups + 2 exp, write UNNORMALIZED f as float2,
//    accumulate out from bf16x2 cons planes (LDS.64)
//  - epilogue: warp-reduce -> inv (stored for scale kernel), out, x_ext
// ---------------------------------------------------------------------------
__global__ __launch_bounds__(256, 4) void fused_kernel(
    const float* __restrict__ x,
    const float* __restrict__ centers,
    const float* __restrict__ widths,
    float* __restrict__ norm_out,
    float* __restrict__ xext_out,
    float* __restrict__ out,
    int write_xext) {
    extern __shared__ unsigned s_cons[];      // 5*NR words = 40 KB
    __shared__ unsigned s_rp[NR];             // 8 KB
    __shared__ float    s_e[8][64];           // 2 KB
    __shared__ float    s_e2[8][8][16];       // 4 KB

    const int tid  = threadIdx.x;
    const int w    = tid >> 5;
    const int lane = tid & 31;
    const int b    = blockIdx.x * 8 + w;

    // cooperative smem fills (vectorized)
    {
        const uint4* src = (const uint4*)g_consP;
        uint4* dst = (uint4*)s_cons;
#pragma unroll
        for (int i = tid; i < (5 * NR) / 4; i += 256) dst[i] = src[i];
        const uint4* rsrc = (const uint4*)g_rpack;
        uint4* rdst = (uint4*)s_rp;
#pragma unroll
        for (int i = tid; i < NR / 4; i += 256) rdst[i] = rsrc[i];
    }

    float xv = (lane < ND) ? x[b * ND + lane] : 0.f;

    float sx = xv;
#pragma unroll
    for (int off = 16; off > 0; off >>= 1)
        sx += __shfl_xor_sync(0xffffffffu, sx, off);
    sx += 1.f;

    if (write_xext) {
        if (lane < ND) xext_out[b * NDP1 + lane] = xv;
        if (lane == ND) xext_out[b * NDP1 + ND] = 1.f;
    }

    // e[d][m] = -(x-c)^2/(2 w^2)
#pragma unroll
    for (int k = lane; k < 64; k += 32) {
        int d = k >> 2, m = k & 3;
        float c  = centers[d * NM + m];
        float wd = widths[d * NM + m];
        float xd = __shfl_sync(0xffffffffu, xv, d);
        float dx = xd - c;
        s_e[w][k] = -(dx * dx) / (2.f * wd * wd);
    }
    __syncwarp();
#pragma unroll
    for (int k = lane; k < 128; k += 32) {
        int t = k >> 4, i = k & 15;
        s_e2[w][t][i] = s_e[w][(2 * t) * 4 + (i & 3)] +
                        s_e[w][(2 * t + 1) * 4 + (i >> 2)];
    }
    __syncthreads();

    float acc[NC];
#pragma unroll
    for (int c = 0; c < NC; ++c) acc[c] = 0.f;
    float sum = 0.f;

    float2* np = (float2*)(norm_out + (size_t)b * NR) + lane;
    const float (*e2)[16] = s_e2[w];

#pragma unroll 8
    for (int i = 0; i < 32; ++i) {
        const int q = i * 32 + lane;              // rule pair index
        uint2 pp = ((const uint2*)s_rp)[q];       // rules 2q, 2q+1
        float s0 = e2[0][pp.x & 15];
        float s1 = e2[0][pp.y & 15];
#pragma unroll
        for (int t = 1; t < 8; ++t) {
            s0 += e2[t][(pp.x >> (4 * t)) & 15];
            s1 += e2[t][(pp.y >> (4 * t)) & 15];
        }
        float f0 = __expf(s0);
        float f1 = __expf(s1);
        sum += f0 + f1;
        np[i * 32] = make_float2(f0, f1);         // unnormalized
#pragma unroll
        for (int p = 0; p < 5; ++p) {
            uint2 cw = ((const uint2*)(s_cons + p * NR))[q];
            float lo0 = __uint_as_float(cw.x << 16);
            float hi0 = __uint_as_float(cw.x & 0xffff0000u);
            float lo1 = __uint_as_float(cw.y << 16);
            float hi1 = __uint_as_float(cw.y & 0xffff0000u);
            acc[2 * p]     = fmaf(f0, lo0, acc[2 * p]);
            acc[2 * p]     = fmaf(f1, lo1, acc[2 * p]);
            acc[2 * p + 1] = fmaf(f0, hi0, acc[2 * p + 1]);
            acc[2 * p + 1] = fmaf(f1, hi1, acc[2 * p + 1]);
        }
    }

#pragma unroll
    for (int off = 16; off > 0; off >>= 1) {
        sum += __shfl_xor_sync(0xffffffffu, sum, off);
#pragma unroll
        for (int c = 0; c < NC; ++c)
            acc[c] += __shfl_xor_sync(0xffffffffu, acc[c], off);
    }
    const float inv = 1.f / (sum + 1e-9f);

    if (lane == 0) {
        g_inv[b] = inv;
        const float k = inv * sx;
#pragma unroll
        for (int c = 0; c < NC; ++c)
            out[(size_t)b * NC + c] = (acc[c] + MU * sum) * k;
    }
}

// ---------------------------------------------------------------------------
// K2: normalize the fs buffer in place: norm[b][r] *= inv[b].
// One block per batch row (L2-resident traffic, bandwidth-bound).
// ---------------------------------------------------------------------------
__global__ __launch_bounds__(256) void scale_kernel(float* __restrict__ norm) {
    const int b = blockIdx.x;
    const float inv = g_inv[b];
    float4* p = (float4*)(norm + (size_t)b * NR);
#pragma unroll
    for (int i = threadIdx.x; i < NR / 4; i += 256) {
        float4 v = p[i];
        v.x *= inv; v.y *= inv; v.z *= inv; v.w *= inv;
        p[i] = v;
    }
}

// ---------------------------------------------------------------------------
extern "C" void kernel_launch(void* const* d_in, const int* in_sizes, int n_in,
                              void* d_out, int out_size) {
    const float* x       = (const float*)d_in[0];
    const float* centers = (const float*)d_in[1];
    const float* widths  = (const float*)d_in[2];
    const float* cons    = (const float*)d_in[3];
    const int*   rules   = (const int*)d_in[4];
    float* out = (float*)d_out;

    const long long TOTAL = (long long)NB_B * NC + (long long)NB_B * NR +
                            (long long)NB_B * NDP1;

    float* out_p = out;
    float* norm_p;
    float* xext_p = out;
    int write_xext = 0;

    if ((long long)out_size == TOTAL) {
        norm_p = out + (size_t)NB_B * NC;
        xext_p = out + (size_t)NB_B * NC + (size_t)NB_B * NR;
        write_xext = 1;
    } else {
        void* sp = nullptr;
        cudaGetSymbolAddress(&sp, g_norm_scratch);
        norm_p = (float*)sp;
    }

    prep_kernel<<<NR / 8, 256>>>(cons, rules);

    const int smem_bytes = 5 * NR * sizeof(unsigned); // 40960
    cudaFuncSetAttribute(fused_kernel,
                         cudaFuncAttributeMaxDynamicSharedMemorySize,
                         smem_bytes);
    fused_kernel<<<NB_B / 8, 256, smem_bytes>>>(x, centers, widths, norm_p,
                                                xext_p, out_p, write_xext);
    scale_kernel<<<NB_B, 256>>>(norm_p);
}

// round 5
// speedup vs baseline: 2.1118x; 1.1969x over previous
#include <cuda_runtime.h>
#include <cuda_bf16.h>
#include <cstdint>

#define NB_B 4096
#define ND 16
#define NM 4
#define NR 2048
#define NC 10
#define NDP1 17
#define MU 8.5f

// Scratch (device globals are the allowed scratch mechanism)
__device__ unsigned g_consP[5 * NR];   // plane p: bf16x2 of (cons_sum[r,2p]-MU, cons_sum[r,2p+1]-MU)
__device__ unsigned g_rpack[NR];       // 16 dims x 2 bits
__device__ float    g_norm_scratch[(size_t)NB_B * NR]; // fallback only

// morton spread of 16 bits into even bit positions
__device__ __forceinline__ unsigned spread16(unsigned v) {
    v &= 0xFFFFu;
    v = (v | (v << 8)) & 0x00FF00FFu;
    v = (v | (v << 4)) & 0x0F0F0F0Fu;
    v = (v | (v << 2)) & 0x33333333u;
    v = (v | (v << 1)) & 0x55555555u;
    return v;
}

// ---------------------------------------------------------------------------
// K0: warp per rule. Lane j (j<17) loads cons[r,j,0..9]; xor-shuffle tree
// gives every lane the 10 column sums (deterministic). Lane 0 writes the 5
// mean-centered bf16x2 planes. rpack via two ballots + bit interleave.
// ---------------------------------------------------------------------------
__global__ __launch_bounds__(256) void prep_kernel(
    const float* __restrict__ cons, const int* __restrict__ rules) {
    const int gw   = (blockIdx.x * 256 + threadIdx.x) >> 5;  // rule id
    const int lane = threadIdx.x & 31;
    if (gw >= NR) return;

    float s[NC];
#pragma unroll
    for (int c = 0; c < NC; ++c) s[c] = 0.f;
    if (lane < NDP1) {
        const float* row = cons + (size_t)gw * NDP1 * NC + lane * NC;
#pragma unroll
        for (int c = 0; c < NC; ++c) s[c] = row[c];
    }
#pragma unroll
    for (int off = 16; off > 0; off >>= 1)
#pragma unroll
        for (int c = 0; c < NC; ++c)
            s[c] += __shfl_xor_sync(0xffffffffu, s[c], off);

    // rpack: lanes 0..15 hold rule index for dim=lane
    int v = (lane < ND) ? rules[gw * ND + lane] : 0;
    unsigned b0 = __ballot_sync(0xffffffffu, v & 1);
    unsigned b1 = __ballot_sync(0xffffffffu, (v >> 1) & 1);

    if (lane == 0) {
#pragma unroll
        for (int p = 0; p < 5; ++p) {
            __nv_bfloat162 h =
                __floats2bfloat162_rn(s[2 * p] - MU, s[2 * p + 1] - MU);
            g_consP[p * NR + gw] = *(unsigned*)&h;
        }
        g_rpack[gw] = spread16(b0) | (spread16(b1) << 1);
    }
}

// ---------------------------------------------------------------------------
// K1 (fused): 256 thr = 8 warps = 2 batches x 4 warps. Each warp handles
// 8 rule-pair iterations (f kept in registers), block exchanges partial sums
// via smem, then pass 2 writes NORMALIZED norm_fs directly and accumulates
// the output GEMV from L1-resident bf16x2 cons planes (LDG, no smem staging).
// ---------------------------------------------------------------------------
__global__ __launch_bounds__(256, 4) void fused_kernel(
    const float* __restrict__ x,
    const float* __restrict__ centers,
    const float* __restrict__ widths,
    float* __restrict__ norm_out,
    float* __restrict__ xext_out,
    float* __restrict__ out,
    int write_xext) {
    __shared__ float s_e[2][64];
    __shared__ float s_e2[2][8][16];
    __shared__ float s_sum[8];
    __shared__ float s_acc[8][NC];
    __shared__ float s_sx[2];

    const int tid  = threadIdx.x;
    const int w    = tid >> 5;
    const int lane = tid & 31;
    const int wb   = w >> 2;      // batch slot in block (0/1)
    const int qh   = w & 3;       // quarter
    const int b    = blockIdx.x * 2 + wb;

    if (qh == 0) {
        float xv = (lane < ND) ? x[b * ND + lane] : 0.f;
        float sx = xv;
#pragma unroll
        for (int off = 16; off > 0; off >>= 1)
            sx += __shfl_xor_sync(0xffffffffu, sx, off);
        sx += 1.f;
        if (lane == 0) s_sx[wb] = sx;
        if (write_xext) {
            if (lane < ND) xext_out[b * NDP1 + lane] = xv;
            if (lane == ND) xext_out[b * NDP1 + ND] = 1.f;
        }
        // e[d][m] = -(x-c)^2/(2 w^2)
#pragma unroll
        for (int k = lane; k < 64; k += 32) {
            int d = k >> 2, m = k & 3;
            float c  = centers[d * NM + m];
            float wd = widths[d * NM + m];
            float xd = __shfl_sync(0xffffffffu, xv, d);
            float dx = xd - c;
            s_e[wb][k] = -(dx * dx) / (2.f * wd * wd);
        }
        __syncwarp();
        // pair tables: e2[t][i] = e[2t][i&3] + e[2t+1][i>>2]
#pragma unroll
        for (int k = lane; k < 128; k += 32) {
            int t = k >> 4, i = k & 15;
            s_e2[wb][t][i] = s_e[wb][(2 * t) * 4 + (i & 3)] +
                             s_e[wb][(2 * t + 1) * 4 + (i >> 2)];
        }
    }
    __syncthreads();

    const float (*e2)[16] = s_e2[wb];
    const uint2* __restrict__ rp = (const uint2*)g_rpack;

    float f0a[8], f1a[8];
    float sum = 0.f;
#pragma unroll
    for (int k = 0; k < 8; ++k) {
        const int q = (qh * 8 + k) * 32 + lane;   // rule pair index
        uint2 pp = rp[q];
        float s0 = e2[0][pp.x & 15];
        float s1 = e2[0][pp.y & 15];
#pragma unroll
        for (int t = 1; t < 8; ++t) {
            s0 += e2[t][(pp.x >> (4 * t)) & 15];
            s1 += e2[t][(pp.y >> (4 * t)) & 15];
        }
        f0a[k] = __expf(s0);
        f1a[k] = __expf(s1);
        sum += f0a[k] + f1a[k];
    }
#pragma unroll
    for (int off = 16; off > 0; off >>= 1)
        sum += __shfl_xor_sync(0xffffffffu, sum, off);
    if (lane == 0) s_sum[w] = sum;
    __syncthreads();

    const float tot = s_sum[wb * 4] + s_sum[wb * 4 + 1] +
                      s_sum[wb * 4 + 2] + s_sum[wb * 4 + 3];
    const float inv = 1.f / (tot + 1e-9f);

    float acc[NC];
#pragma unroll
    for (int c = 0; c < NC; ++c) acc[c] = 0.f;

    float2* np = (float2*)(norm_out + (size_t)b * NR);
#pragma unroll
    for (int k = 0; k < 8; ++k) {
        const int q = (qh * 8 + k) * 32 + lane;
        const float fn0 = f0a[k] * inv;
        const float fn1 = f1a[k] * inv;
        np[q] = make_float2(fn0, fn1);            // normalized
#pragma unroll
        for (int p = 0; p < 5; ++p) {
            uint2 cw = ((const uint2*)(g_consP + p * NR))[q];
            float lo0 = __uint_as_float(cw.x << 16);
            float hi0 = __uint_as_float(cw.x & 0xffff0000u);
            float lo1 = __uint_as_float(cw.y << 16);
            float hi1 = __uint_as_float(cw.y & 0xffff0000u);
            acc[2 * p]     = fmaf(fn0, lo0, acc[2 * p]);
            acc[2 * p]     = fmaf(fn1, lo1, acc[2 * p]);
            acc[2 * p + 1] = fmaf(fn0, hi0, acc[2 * p + 1]);
            acc[2 * p + 1] = fmaf(fn1, hi1, acc[2 * p + 1]);
        }
    }
#pragma unroll
    for (int off = 16; off > 0; off >>= 1)
#pragma unroll
        for (int c = 0; c < NC; ++c)
            acc[c] += __shfl_xor_sync(0xffffffffu, acc[c], off);
    if (lane == 0) {
#pragma unroll
        for (int c = 0; c < NC; ++c) s_acc[w][c] = acc[c];
    }
    __syncthreads();

    if (qh == 0 && lane < NC) {
        float a = s_acc[wb * 4][lane] + s_acc[wb * 4 + 1][lane] +
                  s_acc[wb * 4 + 2][lane] + s_acc[wb * 4 + 3][lane];
        // out = (sum_r fn*consP + MU * sum_r fn) * sx,  sum_r fn = tot*inv
        out[(size_t)b * NC + lane] = (a + MU * tot * inv) * s_sx[wb];
    }
}

// ---------------------------------------------------------------------------
extern "C" void kernel_launch(void* const* d_in, const int* in_sizes, int n_in,
                              void* d_out, int out_size) {
    const float* x       = (const float*)d_in[0];
    const float* centers = (const float*)d_in[1];
    const float* widths  = (const float*)d_in[2];
    const float* cons    = (const float*)d_in[3];
    const int*   rules   = (const int*)d_in[4];
    float* out = (float*)d_out;

    const long long TOTAL = (long long)NB_B * NC + (long long)NB_B * NR +
                            (long long)NB_B * NDP1;

    float* out_p = out;
    float* norm_p;
    float* xext_p = out;
    int write_xext = 0;

    if ((long long)out_size == TOTAL) {
        norm_p = out + (size_t)NB_B * NC;
        xext_p = out + (size_t)NB_B * NC + (size_t)NB_B * NR;
        write_xext = 1;
    } else {
        void* sp = nullptr;
        cudaGetSymbolAddress(&sp, g_norm_scratch);
        norm_p = (float*)sp;
    }

    prep_kernel<<<NR / 8, 256>>>(cons, rules);   // warp per rule
    fused_kernel<<<NB_B / 2, 256>>>(x, centers, widths, norm_p,
                                    xext_p, out_p, write_xext);
}

// round 6
// speedup vs baseline: 2.2405x; 1.0609x over previous
#include <cuda_runtime.h>
#include <cuda_bf16.h>
#include <cstdint>

#define NB_B 4096
#define ND 16
#define NM 4
#define NR 2048
#define NC 10
#define NDP1 17
#define MU 8.5f

typedef unsigned long long ull;

// Scratch (device globals are the allowed scratch mechanism)
// cons planes, mean-centered bf16x2, laid out per rule-PAIR for LDG.128:
//   g_consA[q] = {p0/evenRule, p0/odd, p1/even, p1/odd}
//   g_consB[q] = {p2/even, p2/odd, p3/even, p3/odd}
//   g_consC[q] = {p4/even, p4/odd}
__device__ uint4    g_consA[NR / 2];
__device__ uint4    g_consB[NR / 2];
__device__ uint2    g_consC[NR / 2];
__device__ unsigned g_rpack[NR];                        // 16 dims x 2 bits
__device__ float    g_norm_scratch[(size_t)NB_B * NR];  // fallback only

__device__ __forceinline__ unsigned spread16(unsigned v) {
    v &= 0xFFFFu;
    v = (v | (v << 8)) & 0x00FF00FFu;
    v = (v | (v << 4)) & 0x0F0F0F0Fu;
    v = (v | (v << 2)) & 0x33333333u;
    v = (v | (v << 1)) & 0x55555555u;
    return v;
}

__device__ __forceinline__ ull pack2(float x, float y) {
    ull r;
    asm("mov.b64 %0, {%1, %2};" : "=l"(r) : "f"(x), "f"(y));
    return r;
}
__device__ __forceinline__ void unpack2(float& x, float& y, ull v) {
    asm("mov.b64 {%0, %1}, %2;" : "=f"(x), "=f"(y) : "l"(v));
}
__device__ __forceinline__ void ffma2(ull& d, ull a, ull b) {
    asm("fma.rn.f32x2 %0, %1, %2, %0;" : "+l"(d) : "l"(a), "l"(b));
}
__device__ __forceinline__ ull fmul2(ull a, ull b) {
    ull r;
    asm("mul.rn.f32x2 %0, %1, %2;" : "=l"(r) : "l"(a), "l"(b));
    return r;
}

// ---------------------------------------------------------------------------
// K0: warp per rule. Shuffle-tree reduces cons[r,:,c] over j; lane 0 writes
// the 5 mean-centered bf16x2 words into the pair-interleaved layout, and
// packs the rule's 16 2-bit indices via ballots.
// ---------------------------------------------------------------------------
__global__ __launch_bounds__(256) void prep_kernel(
    const float* __restrict__ cons, const int* __restrict__ rules) {
    const int gw   = (blockIdx.x * 256 + threadIdx.x) >> 5;  // rule id
    const int lane = threadIdx.x & 31;
    if (gw >= NR) return;

    float s[NC];
#pragma unroll
    for (int c = 0; c < NC; ++c) s[c] = 0.f;
    if (lane < NDP1) {
        const float* row = cons + (size_t)gw * NDP1 * NC + lane * NC;
#pragma unroll
        for (int c = 0; c < NC; ++c) s[c] = row[c];
    }
#pragma unroll
    for (int off = 16; off > 0; off >>= 1)
#pragma unroll
        for (int c = 0; c < NC; ++c)
            s[c] += __shfl_xor_sync(0xffffffffu, s[c], off);

    int v = (lane < ND) ? rules[gw * ND + lane] : 0;
    unsigned b0 = __ballot_sync(0xffffffffu, v & 1);
    unsigned b1 = __ballot_sync(0xffffffffu, (v >> 1) & 1);

    if (lane == 0) {
        const int q = gw >> 1, r1 = gw & 1;
        unsigned wbits[5];
#pragma unroll
        for (int p = 0; p < 5; ++p) {
            __nv_bfloat162 h =
                __floats2bfloat162_rn(s[2 * p] - MU, s[2 * p + 1] - MU);
            wbits[p] = *(unsigned*)&h;
        }
        ((unsigned*)g_consA)[q * 4 + 0 + r1] = wbits[0];
        ((unsigned*)g_consA)[q * 4 + 2 + r1] = wbits[1];
        ((unsigned*)g_consB)[q * 4 + 0 + r1] = wbits[2];
        ((unsigned*)g_consB)[q * 4 + 2 + r1] = wbits[3];
        ((unsigned*)g_consC)[q * 2 + r1]     = wbits[4];
        g_rpack[gw] = spread16(b0) | (spread16(b1) << 1);
    }
}

// ---------------------------------------------------------------------------
// K1 (fused): block = 256 thr = 8 warps = 2 batch-PAIRS x 4 warps.
// Tables interleaved as float2 (batchA, batchB): one LDS.64 per lookup
// serves both batches; rpack/extraction/cons loads amortize x2.
// Packed f32x2 FMA for the output GEMV; packed MUL for normalization;
// packed register stores norm_fs directly.
// ---------------------------------------------------------------------------
__global__ __launch_bounds__(256, 2) void fused_kernel(
    const float* __restrict__ x,
    const float* __restrict__ centers,
    const float* __restrict__ widths,
    float* __restrict__ norm_out,
    float* __restrict__ xext_out,
    float* __restrict__ out,
    int write_xext) {
    __shared__ float  s_e[4][64];
    __shared__ float2 s_tab[2][8][16];   // [pair][table][idx] = (eA, eB)
    __shared__ float  s_sum[8][2];
    __shared__ float  s_acc[8][2][NC];
    __shared__ float  s_sx[4];

    const int tid  = threadIdx.x;
    const int w    = tid >> 5;
    const int lane = tid & 31;
    const int g    = w >> 2;        // batch-pair group (0/1)
    const int qw   = w & 3;         // quarter within group
    const int bbase = blockIdx.x * 4;

    // setup: warps 0..3 each handle batch bbase+w (pair = w>>1, half = w&1)
    if (w < 4) {
        const int b = bbase + w;
        float xv = (lane < ND) ? x[b * ND + lane] : 0.f;
        float sx = xv;
#pragma unroll
        for (int off = 16; off > 0; off >>= 1)
            sx += __shfl_xor_sync(0xffffffffu, sx, off);
        sx += 1.f;
        if (lane == 0) s_sx[w] = sx;
        if (write_xext) {
            if (lane < ND) xext_out[b * NDP1 + lane] = xv;
            if (lane == ND) xext_out[b * NDP1 + ND] = 1.f;
        }
#pragma unroll
        for (int k = lane; k < 64; k += 32) {
            int d = k >> 2, m = k & 3;
            float c  = centers[d * NM + m];
            float wd = widths[d * NM + m];
            float xd = __shfl_sync(0xffffffffu, xv, d);
            float dx = xd - c;
            s_e[w][k] = -(dx * dx) / (2.f * wd * wd);
        }
        __syncwarp();
        const int pr = w >> 1, h = w & 1;
#pragma unroll
        for (int k = lane; k < 128; k += 32) {
            int t = k >> 4, i = k & 15;
            float v = s_e[w][(2 * t) * 4 + (i & 3)] +
                      s_e[w][(2 * t + 1) * 4 + (i >> 2)];
            if (h == 0) s_tab[pr][t][i].x = v;
            else        s_tab[pr][t][i].y = v;
        }
    }
    __syncthreads();

    const float2 (*tab)[16] = s_tab[g];
    const uint2* __restrict__ rp = (const uint2*)g_rpack;

    // ---- pass 1: firing strengths for both batches of the pair ----
    ull  fpA[8], fpB[8];
    float sumA = 0.f, sumB = 0.f;
#pragma unroll
    for (int k = 0; k < 8; ++k) {
        const int q = (qw * 8 + k) * 32 + lane;   // rule-pair index
        uint2 pp = rp[q];
        float2 v0 = tab[0][pp.x & 15];
        float2 v1 = tab[0][pp.y & 15];
        float s0A = v0.x, s0B = v0.y, s1A = v1.x, s1B = v1.y;
#pragma unroll
        for (int t = 1; t < 8; ++t) {
            float2 a = tab[t][(pp.x >> (4 * t)) & 15];
            float2 b2 = tab[t][(pp.y >> (4 * t)) & 15];
            s0A += a.x;  s0B += a.y;
            s1A += b2.x; s1B += b2.y;
        }
        float f0A = __expf(s0A), f1A = __expf(s1A);
        float f0B = __expf(s0B), f1B = __expf(s1B);
        sumA += f0A + f1A;
        sumB += f0B + f1B;
        fpA[k] = pack2(f0A, f1A);
        fpB[k] = pack2(f0B, f1B);
    }
#pragma unroll
    for (int off = 16; off > 0; off >>= 1) {
        sumA += __shfl_xor_sync(0xffffffffu, sumA, off);
        sumB += __shfl_xor_sync(0xffffffffu, sumB, off);
    }
    if (lane == 0) { s_sum[w][0] = sumA; s_sum[w][1] = sumB; }
    __syncthreads();

    const float totA = s_sum[g * 4][0] + s_sum[g * 4 + 1][0] +
                       s_sum[g * 4 + 2][0] + s_sum[g * 4 + 3][0];
    const float totB = s_sum[g * 4][1] + s_sum[g * 4 + 1][1] +
                       s_sum[g * 4 + 2][1] + s_sum[g * 4 + 3][1];
    const float invA = 1.f / (totA + 1e-9f);
    const float invB = 1.f / (totB + 1e-9f);
    const ull invA2 = pack2(invA, invA);
    const ull invB2 = pack2(invB, invB);

    // ---- pass 2: normalized write + packed GEMV ----
    ull acc2A[NC], acc2B[NC];
#pragma unroll
    for (int c = 0; c < NC; ++c) { acc2A[c] = 0ull; acc2B[c] = 0ull; }

    const int bA = bbase + g * 2, bB = bA + 1;
    ull* npA = (ull*)(norm_out + (size_t)bA * NR);
    ull* npB = (ull*)(norm_out + (size_t)bB * NR);

#pragma unroll
    for (int k = 0; k < 8; ++k) {
        const int q = (qw * 8 + k) * 32 + lane;
        const ull aA = fmul2(fpA[k], invA2);      // (fn_even, fn_odd) batch A
        const ull aB = fmul2(fpB[k], invB2);
        npA[q] = aA;                              // normalized norm_fs
        npB[q] = aB;

        uint4 cA = g_consA[q];
        uint4 cB = g_consB[q];
        uint2 cC = g_consC[q];
        const unsigned we[5] = {cA.x, cA.z, cB.x, cB.z, cC.x};
        const unsigned wo[5] = {cA.y, cA.w, cB.y, cB.w, cC.y};
#pragma unroll
        for (int p = 0; p < 5; ++p) {
            ull blo = pack2(__uint_as_float(we[p] << 16),
                            __uint_as_float(wo[p] << 16));
            ull bhi = pack2(__uint_as_float(we[p] & 0xffff0000u),
                            __uint_as_float(wo[p] & 0xffff0000u));
            ffma2(acc2A[2 * p],     aA, blo);
            ffma2(acc2A[2 * p + 1], aA, bhi);
            ffma2(acc2B[2 * p],     aB, blo);
            ffma2(acc2B[2 * p + 1], aB, bhi);
        }
    }

    float accA[NC], accB[NC];
#pragma unroll
    for (int c = 0; c < NC; ++c) {
        float ax, ay, bx, by;
        unpack2(ax, ay, acc2A[c]);
        unpack2(bx, by, acc2B[c]);
        accA[c] = ax + ay;
        accB[c] = bx + by;
    }
#pragma unroll
    for (int off = 16; off > 0; off >>= 1)
#pragma unroll
        for (int c = 0; c < NC; ++c) {
            accA[c] += __shfl_xor_sync(0xffffffffu, accA[c], off);
            accB[c] += __shfl_xor_sync(0xffffffffu, accB[c], off);
        }
    if (lane == 0) {
#pragma unroll
        for (int c = 0; c < NC; ++c) {
            s_acc[w][0][c] = accA[c];
            s_acc[w][1][c] = accB[c];
        }
    }
    __syncthreads();

    if (tid < 40) {
        const int gg = tid / 20, h = (tid / 10) % 2, c = tid % 10;
        float a = s_acc[gg * 4][h][c] + s_acc[gg * 4 + 1][h][c] +
                  s_acc[gg * 4 + 2][h][c] + s_acc[gg * 4 + 3][h][c];
        float tot = s_sum[gg * 4][h] + s_sum[gg * 4 + 1][h] +
                    s_sum[gg * 4 + 2][h] + s_sum[gg * 4 + 3][h];
        float inv = 1.f / (tot + 1e-9f);
        const int b = bbase + gg * 2 + h;
        out[(size_t)b * NC + c] = (a + MU * tot * inv) * s_sx[gg * 2 + h];
    }
}

// ---------------------------------------------------------------------------
extern "C" void kernel_launch(void* const* d_in, const int* in_sizes, int n_in,
                              void* d_out, int out_size) {
    const float* x       = (const float*)d_in[0];
    const float* centers = (const float*)d_in[1];
    const float* widths  = (const float*)d_in[2];
    const float* cons    = (const float*)d_in[3];
    const int*   rules   = (const int*)d_in[4];
    float* out = (float*)d_out;

    const long long TOTAL = (long long)NB_B * NC + (long long)NB_B * NR +
                            (long long)NB_B * NDP1;

    float* out_p = out;
    float* norm_p;
    float* xext_p = out;
    int write_xext = 0;

    if ((long long)out_size == TOTAL) {
        norm_p = out + (size_t)NB_B * NC;
        xext_p = out + (size_t)NB_B * NC + (size_t)NB_B * NR;
        write_xext = 1;
    } else {
        void* sp = nullptr;
        cudaGetSymbolAddress(&sp, g_norm_scratch);
        norm_p = (float*)sp;
    }

    prep_kernel<<<NR / 8, 256>>>(cons, rules);
    fused_kernel<<<NB_B / 4, 256>>>(x, centers, widths, norm_p,
                                    xext_p, out_p, write_xext);
}